// round 16
// baseline (speedup 1.0000x reference)
#include <cuda_runtime.h>
#include <cuda_fp8.h>
#include <cstdint>
#include <cstddef>

#define MM 16384
#define KK 4096
#define NN 4096
#define KTILES (KK/128)   // 32
#define NTILES (NN/128)   // 32
#define MTILES (MM/128)   // 128
#define TILE_BYTES 16384
#define STAGES 3
#define STAGE_BYTES (2*TILE_BYTES)            // A(16KB) + B(16KB)
#define SMEM_DYN (1024 + STAGES*STAGE_BYTES)  // 99328 B -> two CTAs/SM by smem
#define NTG 288           // 8 compute warps (64x32 tiles) + 1 producer warp

// Evidence log: plain compute_103 pass (R2) -> mma.sync fp8 runs. R6 = 406us
// (occ 2: regs <=113 at 288thr, smem 99KB). R14: same GEMM @132KB smem -> occ1,
// 5.5x slower. R15: same GEMM but epilogue computed 1/(sx*sw) with live
// accumulators -> div temps pushed regs past 113 -> occ 1 -> 1401us.
// This round: R6-exact epilogue (single precomputed g_scales[2] load) AND
// __launch_bounds__(288,2) to pin the 113-reg / occ-2 compile.

// ---------------- scratch (device globals: allocation-free) ----------------
__device__ __align__(1024) unsigned char g_xq[(size_t)MM*KK]; // 64 MB, tiled+swizzled
__device__ __align__(1024) unsigned char g_wq[(size_t)NN*KK]; // 16 MB, tiled+swizzled
__device__ unsigned g_absmax[2];  // zero-init; atomicMax idempotent across replays
__device__ float g_scales[3];     // sx, sw, 1/(sx*sw) — written by scale_kernel

// ---------------- PTX helpers ----------------
__device__ __forceinline__ uint32_t smem_u32(const void* p) {
    uint32_t a;
    asm("{ .reg .u64 t; cvta.to.shared.u64 t, %1; cvt.u32.u64 %0, t; }" : "=r"(a) : "l"(p));
    return a;
}
__device__ __forceinline__ uint32_t elect_one_pred() {
    uint32_t p;
    asm volatile("{ .reg .pred p; elect.sync _|p, 0xFFFFFFFF; selp.b32 %0, 1, 0, p; }" : "=r"(p));
    return p;
}
#define MBARRIER_INIT(addr, cnt) \
    asm volatile("mbarrier.init.shared.b64 [%0], %1;" :: "r"(addr), "r"(cnt) : "memory")
#define MBARRIER_EXPECT_TX(addr, bytes) \
    asm volatile("mbarrier.arrive.expect_tx.shared.b64 _, [%0], %1;" :: "r"(addr), "r"(bytes) : "memory")
#define MBARRIER_ARRIVE(addr) \
    asm volatile("mbarrier.arrive.shared.b64 _, [%0];" :: "r"(addr) : "memory")
#define MBARRIER_WAIT_PARITY(mbar_smem_addr, phase_parity) do { \
    uint32_t _mbar = (uint32_t)(mbar_smem_addr); \
    uint32_t _parity = (uint32_t)(phase_parity); \
    uint32_t _done; \
    asm volatile("{ .reg .pred p; mbarrier.try_wait.parity.acquire.cta.shared::cta.b64 p, [%1], %2; selp.b32 %0, 1, 0, p; }" \
        : "=r"(_done) : "r"(_mbar), "r"(_parity) : "memory"); \
    if (!_done) { \
        asm volatile("{ .reg .pred P1; WAIT_LOOP_%=: mbarrier.try_wait.parity.acquire.cta.shared::cta.b64 P1, [%0], %1, 0x989680; @P1 bra.uni WAIT_DONE_%=; bra.uni WAIT_LOOP_%=; WAIT_DONE_%=: }" \
            :: "r"(_mbar), "r"(_parity) : "memory"); \
    } \
} while(0)
#define MBARRIER_WAIT_PARITY_RELAXED(mbar_smem_addr, phase_parity) do { \
    uint32_t _mbar = (uint32_t)(mbar_smem_addr); \
    uint32_t _parity = (uint32_t)(phase_parity); \
    uint32_t _done; \
    asm volatile("{ .reg .pred p; mbarrier.try_wait.parity.relaxed.cta.shared::cta.b64 p, [%1], %2, 0x989680; selp.b32 %0, 1, 0, p; }" \
        : "=r"(_done) : "r"(_mbar), "r"(_parity) : "memory"); \
    if (!_done) { \
        asm volatile("{ .reg .pred P1; WAIT_LOOP_%=: mbarrier.try_wait.parity.relaxed.cta.shared::cta.b64 P1, [%0], %1, 0x989680; @P1 bra.uni WAIT_DONE_%=; bra.uni WAIT_LOOP_%=; WAIT_DONE_%=: }" \
            :: "r"(_mbar), "r"(_parity) : "memory"); \
    } \
} while(0)

__device__ __forceinline__ void bulk_g2s(uint32_t dst, const void* src, uint32_t bytes, uint32_t mbar) {
    asm volatile(
        "cp.async.bulk.shared::cluster.global.mbarrier::complete_tx::bytes [%0], [%1], %2, [%3];"
        :: "r"(dst), "l"(src), "r"(bytes), "r"(mbar) : "memory");
}

__device__ __forceinline__ unsigned swz128(unsigned off) { return off ^ ((off >> 3) & 0x70); }
__device__ __forceinline__ unsigned char q_e4m3(float v) {
    return (unsigned char)__nv_cvt_float_to_fp8(v, __NV_SATFINITE, __NV_E4M3);
}
__device__ __forceinline__ void ldsm4(unsigned& r0, unsigned& r1, unsigned& r2, unsigned& r3, uint32_t addr) {
    asm volatile("ldmatrix.sync.aligned.m8n8.x4.shared.b16 {%0,%1,%2,%3}, [%4];"
        : "=r"(r0), "=r"(r1), "=r"(r2), "=r"(r3) : "r"(addr));
}
__device__ __forceinline__ void mma_e4m3(float* d, const unsigned* a, const unsigned* b) {
    asm volatile("mma.sync.aligned.m16n8k32.row.col.f32.e4m3.e4m3.f32 "
        "{%0,%1,%2,%3}, {%4,%5,%6,%7}, {%8,%9}, {%0,%1,%2,%3};"
        : "+f"(d[0]), "+f"(d[1]), "+f"(d[2]), "+f"(d[3])
        : "r"(a[0]), "r"(a[1]), "r"(a[2]), "r"(a[3]), "r"(b[0]), "r"(b[1]));
}

// ---------------- phase kernels ----------------
__global__ void absmax_both_kernel(const float* __restrict__ x, const float* __restrict__ w) {
    size_t tid0 = (size_t)blockIdx.x * blockDim.x + threadIdx.x;
    size_t stride = (size_t)gridDim.x * blockDim.x;
    const float4* p4 = (const float4*)x;
    unsigned m0 = 0;
    for (size_t i = tid0; i < (size_t)MM * KK / 4; i += stride) {
        float4 v = p4[i];
        unsigned a;
        a = __float_as_uint(v.x) & 0x7fffffffu; m0 = max(m0, a);
        a = __float_as_uint(v.y) & 0x7fffffffu; m0 = max(m0, a);
        a = __float_as_uint(v.z) & 0x7fffffffu; m0 = max(m0, a);
        a = __float_as_uint(v.w) & 0x7fffffffu; m0 = max(m0, a);
    }
    m0 = __reduce_max_sync(0xffffffffu, m0);
    if ((threadIdx.x & 31) == 0) atomicMax(&g_absmax[0], m0);

    const float4* q4 = (const float4*)w;
    unsigned m1 = 0;
    for (size_t i = tid0; i < (size_t)KK * NN / 4; i += stride) {
        float4 v = q4[i];
        unsigned a;
        a = __float_as_uint(v.x) & 0x7fffffffu; m1 = max(m1, a);
        a = __float_as_uint(v.y) & 0x7fffffffu; m1 = max(m1, a);
        a = __float_as_uint(v.z) & 0x7fffffffu; m1 = max(m1, a);
        a = __float_as_uint(v.w) & 0x7fffffffu; m1 = max(m1, a);
    }
    m1 = __reduce_max_sync(0xffffffffu, m1);
    if ((threadIdx.x & 31) == 0) atomicMax(&g_absmax[1], m1);
}

__global__ void scale_kernel() {
    float ax = __uint_as_float(g_absmax[0]);
    float aw = __uint_as_float(g_absmax[1]);
    float sx = 448.0f / ax, sw = 448.0f / aw;
    g_scales[0] = sx; g_scales[1] = sw; g_scales[2] = 1.0f / (sx * sw);
}

// Fused quantize: blocks [0, 16384) handle x (1 thread / 16B output chunk),
// blocks [16384, 17408) handle w (transpose via smem, one 128x128 tile each).
#define QX_BLOCKS ((MM / 16) * KK / 256)   // 16384
__global__ void quantize_fused_kernel(const float* __restrict__ x, const float* __restrict__ w) {
    __shared__ unsigned char sm[128 * 132];
    unsigned bid = blockIdx.x, t = threadIdx.x;
    if (bid < QX_BLOCKS) {
        // ---- x path: [M,K] fp32 -> g_xq tiled (mtile,ktile) 128x128B SW128 ----
        float sx = g_scales[0];
        unsigned idx = bid * 256 + t;     // [0, M*K/16)
        unsigned row = idx >> 8;          // K/16 = 256 chunks per row
        unsigned kc  = idx & 255;
        unsigned ktile = kc >> 3, c16 = kc & 7;
        const float4* src = (const float4*)(x + (size_t)row * KK + ktile * 128 + c16 * 16);
        unsigned out[4];
#pragma unroll
        for (int i = 0; i < 4; i++) {
            float4 v = src[i];
            unsigned b0 = q_e4m3(v.x * sx), b1 = q_e4m3(v.y * sx);
            unsigned b2 = q_e4m3(v.z * sx), b3 = q_e4m3(v.w * sx);
            out[i] = b0 | (b1 << 8) | (b2 << 16) | (b3 << 24);
        }
        unsigned tile = (row >> 7) * KTILES + ktile;
        unsigned r = row & 127;
        *(uint4*)(g_xq + (size_t)tile * TILE_BYTES + swz128(r * 128 + c16 * 16)) =
            make_uint4(out[0], out[1], out[2], out[3]);
    } else {
        // ---- w path: [K,N] fp32 -> transpose+quantize -> g_wq tiled SW128 ----
        unsigned bid2 = bid - QX_BLOCKS;            // [0, 1024)
        float swc = g_scales[1];
        unsigned ntile = bid2 >> 5, ktile = bid2 & 31;
#pragma unroll 4
        for (int i = 0; i < 16; i++) {
            unsigned f = t + i * 256;        // [0, 4096) float4 slots
            unsigned kk = f >> 5, n4 = f & 31;
            float4 v = *(const float4*)(w + (size_t)(ktile * 128 + kk) * NN + ntile * 128 + n4 * 4);
            unsigned nn = n4 * 4;
            sm[(nn + 0) * 132 + kk] = q_e4m3(v.x * swc);
            sm[(nn + 1) * 132 + kk] = q_e4m3(v.y * swc);
            sm[(nn + 2) * 132 + kk] = q_e4m3(v.z * swc);
            sm[(nn + 3) * 132 + kk] = q_e4m3(v.w * swc);
        }
        __syncthreads();
        size_t tbase = (size_t)(ntile * KTILES + ktile) * TILE_BYTES;
#pragma unroll
        for (int i = 0; i < 4; i++) {
            unsigned c = t + i * 256;        // [0, 1024) 16B chunks
            unsigned r = c >> 3, c16 = c & 7;
            unsigned base = r * 132 + c16 * 16;
            unsigned o0 = *(const unsigned*)(sm + base + 0);
            unsigned o1 = *(const unsigned*)(sm + base + 4);
            unsigned o2 = *(const unsigned*)(sm + base + 8);
            unsigned o3 = *(const unsigned*)(sm + base + 12);
            *(uint4*)(g_wq + tbase + swz128(r * 128 + c16 * 16)) = make_uint4(o0, o1, o2, o3);
        }
    }
}

// ---------------- GEMM (R6-exact body; occ 2 pinned) ----------------
// 4096 CTAs (128x128 tiles), 288 threads: 8 compute warps (2 M x 4 N grid of
// 64x32 warp tiles) + 1 producer warp. 3-stage cp.async.bulk pipeline, 99KB
// smem. launch_bounds(288,2) pins regs <=113 -> 2 CTAs/SM. Epilogue loads the
// single precomputed g_scales[2] (NO divides with live accumulators).
__global__ void __launch_bounds__(NTG, 2) gemm_kernel(float* __restrict__ out) {
    extern __shared__ char dsm[];
    __shared__ __align__(8) unsigned long long bars[2 * STAGES]; // full[s], consumed[s]

    unsigned tid = threadIdx.x, wid = tid >> 5, lane = tid & 31;
    unsigned tile_base = (smem_u32(dsm) + 1023u) & ~1023u;
    unsigned bars_a = smem_u32(bars);
    unsigned mtile = blockIdx.x >> 5, ntile = blockIdx.x & 31;

    const unsigned char* Ag = g_xq + (size_t)mtile * KTILES * TILE_BYTES;
    const unsigned char* Bg = g_wq + (size_t)ntile * KTILES * TILE_BYTES;

    if (tid == 0) {
#pragma unroll
        for (int s = 0; s < STAGES; s++) {
            MBARRIER_INIT(bars_a + 8 * s, 1);              // full[s] (tx-based)
            MBARRIER_INIT(bars_a + 8 * (STAGES + s), 8);   // consumed[s] (8 warps)
        }
    }
    __syncthreads();

    if (wid == 8) {
        // producer warp
        if (elect_one_pred()) {
            for (int kt = 0; kt < KTILES; kt++) {
                int s = kt % STAGES, u = kt / STAGES;
                if (u > 0) MBARRIER_WAIT_PARITY_RELAXED(bars_a + 8 * (STAGES + s), (u - 1) & 1);
                uint32_t full = bars_a + 8 * s;
                MBARRIER_EXPECT_TX(full, (uint32_t)STAGE_BYTES);
                uint32_t dst = tile_base + (unsigned)s * (unsigned)STAGE_BYTES;
                bulk_g2s(dst,              Ag + (size_t)kt * TILE_BYTES, TILE_BYTES, full);
                bulk_g2s(dst + TILE_BYTES, Bg + (size_t)kt * TILE_BYTES, TILE_BYTES, full);
            }
        }
    } else {
        // 8 compute warps: 2(M) x 4(N); each computes 64x32 of the 128x128 tile
        unsigned wm = wid >> 2, wn = wid & 3;
        float d[4][4][4];
#pragma unroll
        for (int i = 0; i < 4; i++)
#pragma unroll
            for (int j = 0; j < 4; j++)
#pragma unroll
                for (int k = 0; k < 4; k++) d[i][j][k] = 0.0f;

        // per-lane ldmatrix addressing into SW128-swizzled 128x128B tiles
        unsigned xorm = (lane & 7) << 4;
        unsigned aRow[4], bRow[2];
#pragma unroll
        for (int am = 0; am < 4; am++)
            aRow[am] = (wm * 64 + am * 16 + ((lane >> 3) & 1) * 8 + (lane & 7)) * 128;
#pragma unroll
        for (int p = 0; p < 2; p++)
            bRow[p] = (wn * 32 + p * 16 + (lane >> 4) * 8 + (lane & 7)) * 128;
        unsigned aColBase = (lane >> 4) << 4;         // 0 or 16
        unsigned bColBase = ((lane >> 3) & 1) << 4;   // 0 or 16

        for (int kt = 0; kt < KTILES; kt++) {
            int s = kt % STAGES, u = kt / STAGES;
            MBARRIER_WAIT_PARITY(bars_a + 8 * s, u & 1);
            uint32_t sA = tile_base + (unsigned)s * (unsigned)STAGE_BYTES;
            uint32_t sB = sA + TILE_BYTES;
#pragma unroll
            for (int kk = 0; kk < 4; kk++) {
                unsigned acol = ((unsigned)(kk * 32) + aColBase) ^ xorm;
                unsigned bcol = ((unsigned)(kk * 32) + bColBase) ^ xorm;
                unsigned a[4][4];
#pragma unroll
                for (int am = 0; am < 4; am++)
                    ldsm4(a[am][0], a[am][1], a[am][2], a[am][3], sA + aRow[am] + acol);
                unsigned b[4][2];
#pragma unroll
                for (int p = 0; p < 2; p++)
                    ldsm4(b[2 * p][0], b[2 * p][1], b[2 * p + 1][0], b[2 * p + 1][1],
                          sB + bRow[p] + bcol);
#pragma unroll
                for (int am = 0; am < 4; am++)
#pragma unroll
                    for (int bn = 0; bn < 4; bn++)
                        mma_e4m3(d[am][bn], a[am], b[bn]);
            }
            __syncwarp();
            if (lane == 0) MBARRIER_ARRIVE(bars_a + 8 * (STAGES + s));
        }

        // epilogue: single precomputed scale load (R6-exact)
        float inv = g_scales[2];
        unsigned gID = lane >> 2, tID = lane & 3;
#pragma unroll
        for (int am = 0; am < 4; am++) {
            unsigned row0 = mtile * 128 + wm * 64 + am * 16 + gID;
#pragma unroll
            for (int bn = 0; bn < 4; bn++) {
                unsigned col = ntile * 128 + wn * 32 + bn * 8 + tID * 2;
                float2 v0 = make_float2(d[am][bn][0] * inv, d[am][bn][1] * inv);
                float2 v1 = make_float2(d[am][bn][2] * inv, d[am][bn][3] * inv);
                *(float2*)(out + (size_t)row0 * NN + col) = v0;
                *(float2*)(out + (size_t)(row0 + 8) * NN + col) = v1;
            }
        }
    }
}

// ---------------- launch ----------------
extern "C" void kernel_launch(void* const* d_in, const int* in_sizes, int n_in,
                              void* d_out, int out_size) {
    (void)in_sizes; (void)n_in; (void)out_size;
    const float* x = (const float*)d_in[0];
    const float* w = (const float*)d_in[1];
    float* out = (float*)d_out;

    cudaFuncSetAttribute(gemm_kernel, cudaFuncAttributeMaxDynamicSharedMemorySize, SMEM_DYN);

    absmax_both_kernel<<<2048, 256>>>(x, w);
    scale_kernel<<<1, 1>>>();
    quantize_fused_kernel<<<QX_BLOCKS + NTILES * KTILES, 256>>>(x, w);
    gemm_kernel<<<MTILES * NTILES, NTG, SMEM_DYN>>>(out);
}

// round 17
// speedup vs baseline: 4.9101x; 4.9101x over previous
#include <cuda_runtime.h>
#include <cuda_fp8.h>
#include <cstdint>
#include <cstddef>

#define MM 16384
#define KK 4096
#define NN 4096
#define KTILES (KK/128)   // 32
#define NTILES (NN/128)   // 32
#define MTILES (MM/128)   // 128
#define TILE_BYTES 16384
#define STAGES 3
#define STAGE_BYTES (2*TILE_BYTES)
#define SMEM_DYN (1024 + STAGES*STAGE_BYTES)  // 99328 B
#define NT 288            // 8 compute warps + 1 producer warp (R6-exact)

// ROOT CAUSE (R16 analysis): R6 (406us) printed rel_err 2.308e-07; every
// mma.sync-only round prints 9.187e-08. Different arithmetic -> R6 executed the
// TCGEN05 path: the harness also builds an sm_103a pass, where
// __CUDA_ARCH_FEAT_SM103_ALL is defined and the guarded tcgen05 body compiles;
// the driver loads that cubin. R7+ deleted the dual path and optimized the
// legacy QMMA path (~1.3ms HW ceiling). This round restores the R6 dual-path
// gemm byte-for-byte + consolidated phase launches.
#if defined(__CUDA_ARCH__) && (defined(__CUDA_ARCH_FEAT_SM103_ALL) || defined(__CUDA_ARCH_FEAT_SM100_ALL) || defined(__CUDA_ARCH_FEAT_SM101_ALL))
#define USE_TCGEN05 1
#else
#define USE_TCGEN05 0
#endif

// ---------------- scratch (device globals: allocation-free) ----------------
__device__ __align__(1024) unsigned char g_xq[(size_t)MM*KK]; // 64 MB, tiled+swizzled
__device__ __align__(1024) unsigned char g_wq[(size_t)NN*KK]; // 16 MB, tiled+swizzled
__device__ unsigned g_absmax[2];  // zero-init; atomicMax idempotent across replays
__device__ float g_scales[3];     // sx, sw, 1/(sx*sw)

// ---------------- PTX helpers (plain-target legal) ----------------
__device__ __forceinline__ uint32_t smem_u32(const void* p) {
    uint32_t a;
    asm("{ .reg .u64 t; cvta.to.shared.u64 t, %1; cvt.u32.u64 %0, t; }" : "=r"(a) : "l"(p));
    return a;
}
__device__ __forceinline__ uint32_t elect_one_pred() {
    uint32_t p;
    asm volatile("{ .reg .pred p; elect.sync _|p, 0xFFFFFFFF; selp.b32 %0, 1, 0, p; }" : "=r"(p));
    return p;
}
#define MBARRIER_INIT(addr, cnt) \
    asm volatile("mbarrier.init.shared.b64 [%0], %1;" :: "r"(addr), "r"(cnt) : "memory")
#define MBARRIER_EXPECT_TX(addr, bytes) \
    asm volatile("mbarrier.arrive.expect_tx.shared.b64 _, [%0], %1;" :: "r"(addr), "r"(bytes) : "memory")
#define MBARRIER_ARRIVE(addr) \
    asm volatile("mbarrier.arrive.shared.b64 _, [%0];" :: "r"(addr) : "memory")
#define MBARRIER_WAIT_PARITY(mbar_smem_addr, phase_parity) do { \
    uint32_t _mbar = (uint32_t)(mbar_smem_addr); \
    uint32_t _parity = (uint32_t)(phase_parity); \
    uint32_t _done; \
    asm volatile("{ .reg .pred p; mbarrier.try_wait.parity.acquire.cta.shared::cta.b64 p, [%1], %2; selp.b32 %0, 1, 0, p; }" \
        : "=r"(_done) : "r"(_mbar), "r"(_parity) : "memory"); \
    if (!_done) { \
        asm volatile("{ .reg .pred P1; WAIT_LOOP_%=: mbarrier.try_wait.parity.acquire.cta.shared::cta.b64 P1, [%0], %1, 0x989680; @P1 bra.uni WAIT_DONE_%=; bra.uni WAIT_LOOP_%=; WAIT_DONE_%=: }" \
            :: "r"(_mbar), "r"(_parity) : "memory"); \
    } \
} while(0)
#define MBARRIER_WAIT_PARITY_RELAXED(mbar_smem_addr, phase_parity) do { \
    uint32_t _mbar = (uint32_t)(mbar_smem_addr); \
    uint32_t _parity = (uint32_t)(phase_parity); \
    uint32_t _done; \
    asm volatile("{ .reg .pred p; mbarrier.try_wait.parity.relaxed.cta.shared::cta.b64 p, [%1], %2, 0x989680; selp.b32 %0, 1, 0, p; }" \
        : "=r"(_done) : "r"(_mbar), "r"(_parity) : "memory"); \
    if (!_done) { \
        asm volatile("{ .reg .pred P1; WAIT_LOOP_%=: mbarrier.try_wait.parity.relaxed.cta.shared::cta.b64 P1, [%0], %1, 0x989680; @P1 bra.uni WAIT_DONE_%=; bra.uni WAIT_LOOP_%=; WAIT_DONE_%=: }" \
            :: "r"(_mbar), "r"(_parity) : "memory"); \
    } \
} while(0)

__device__ __forceinline__ void bulk_g2s(uint32_t dst, const void* src, uint32_t bytes, uint32_t mbar) {
    asm volatile(
        "cp.async.bulk.shared::cluster.global.mbarrier::complete_tx::bytes [%0], [%1], %2, [%3];"
        :: "r"(dst), "l"(src), "r"(bytes), "r"(mbar) : "memory");
}

__device__ __forceinline__ unsigned swz128(unsigned off) { return off ^ ((off >> 3) & 0x70); }
__device__ __forceinline__ unsigned char q_e4m3(float v) {
    return (unsigned char)__nv_cvt_float_to_fp8(v, __NV_SATFINITE, __NV_E4M3);
}

#if USE_TCGEN05
// ---------------- tcgen05 helpers (sm_103a pass only) ----------------
#define TCGEN05_ALLOC(smem_addr, nCols) \
    asm volatile("tcgen05.alloc.cta_group::1.sync.aligned.shared::cta.b32 [%0], %1;" \
        :: "r"((uint32_t)(smem_addr)), "r"((uint32_t)(nCols)) : "memory")
#define TCGEN05_DEALLOC(tmem_addr, nCols) \
    asm volatile("tcgen05.dealloc.cta_group::1.sync.aligned.b32 %0, %1;" :: "r"(tmem_addr), "r"((uint32_t)(nCols)))
#define TCGEN05_RELINQUISH() \
    asm volatile("tcgen05.relinquish_alloc_permit.cta_group::1.sync.aligned;")
#define TCGEN05_WAIT_ST() asm volatile("tcgen05.wait::st.sync.aligned;" ::: "memory")
#define TCGEN05_WAIT_LD() asm volatile("tcgen05.wait::ld.sync.aligned;" ::: "memory")
#define TCGEN05_FENCE_BEFORE() asm volatile("tcgen05.fence::before_thread_sync;" ::: "memory")
#define TCGEN05_FENCE_AFTER()  asm volatile("tcgen05.fence::after_thread_sync;" ::: "memory")
#define TCGEN05_COMMIT(mbar) \
    asm volatile("tcgen05.commit.cta_group::1.mbarrier::arrive::one.shared::cluster.b64 [%0];" \
        :: "r"((uint32_t)(mbar)) : "memory")
#define TCGEN05_ST_32X32B_X1(tmem_addr, r0) \
    asm volatile("tcgen05.st.sync.aligned.32x32b.x1.b32 [%0], {%1};" :: "r"(tmem_addr), "r"(r0) : "memory")
#define TCGEN05_LD_32X32B_X32(r, tmem_addr) \
    asm volatile( \
        "tcgen05.ld.sync.aligned.32x32b.x32.b32 " \
        "{%0, %1, %2, %3, %4, %5, %6, %7, " \
        " %8, %9, %10, %11, %12, %13, %14, %15, " \
        " %16, %17, %18, %19, %20, %21, %22, %23, " \
        " %24, %25, %26, %27, %28, %29, %30, %31}, [%32];" \
        : "=r"((r)[0]),  "=r"((r)[1]),  "=r"((r)[2]),  "=r"((r)[3]), \
          "=r"((r)[4]),  "=r"((r)[5]),  "=r"((r)[6]),  "=r"((r)[7]), \
          "=r"((r)[8]),  "=r"((r)[9]),  "=r"((r)[10]), "=r"((r)[11]), \
          "=r"((r)[12]), "=r"((r)[13]), "=r"((r)[14]), "=r"((r)[15]), \
          "=r"((r)[16]), "=r"((r)[17]), "=r"((r)[18]), "=r"((r)[19]), \
          "=r"((r)[20]), "=r"((r)[21]), "=r"((r)[22]), "=r"((r)[23]), \
          "=r"((r)[24]), "=r"((r)[25]), "=r"((r)[26]), "=r"((r)[27]), \
          "=r"((r)[28]), "=r"((r)[29]), "=r"((r)[30]), "=r"((r)[31]) \
        : "r"(tmem_addr))

// SW128 smem descriptor (K-major, LBO=1, SBO=64, Blackwell version bit)
#define SMEM_DESC_BASE_SW128 \
    ((uint64_t(2) << 61) | (uint64_t(1) << 46) | (uint64_t(64) << 32) | (uint64_t(1) << 16))
#define MAKE_SMEM_DESC(base_addr) (SMEM_DESC_BASE_SW128 | ((uint64_t)((base_addr) >> 4) & 0x3FFF))

__device__ __forceinline__ void mma_mxf8_ss(
    uint32_t d_tmem, uint64_t a_desc, uint64_t b_desc, uint32_t idesc,
    uint32_t sfa_tmem, uint32_t sfb_tmem, uint32_t enable) {
    asm volatile(
        "{\n\t.reg .pred p;\n\tsetp.ne.u32 p, %6, 0;\n\t"
        "tcgen05.mma.cta_group::1.kind::mxf8f6f4.block_scale.scale_vec::1X "
        "[%0], %1, %2, %3, [%4], [%5], p;\n\t}"
        :: "r"(d_tmem), "l"(a_desc), "l"(b_desc), "r"(idesc),
           "r"(sfa_tmem), "r"(sfb_tmem), "r"(enable)
        : "memory");
}
#else
// ---------------- mma.sync fallback helpers (plain-target) ----------------
__device__ __forceinline__ void ldsm4(unsigned& r0, unsigned& r1, unsigned& r2, unsigned& r3, uint32_t addr) {
    asm volatile("ldmatrix.sync.aligned.m8n8.x4.shared.b16 {%0,%1,%2,%3}, [%4];"
        : "=r"(r0), "=r"(r1), "=r"(r2), "=r"(r3) : "r"(addr));
}
__device__ __forceinline__ void mma_e4m3(float* d, const unsigned* a, const unsigned* b) {
    asm volatile("mma.sync.aligned.m16n8k32.row.col.f32.e4m3.e4m3.f32 "
        "{%0,%1,%2,%3}, {%4,%5,%6,%7}, {%8,%9}, {%0,%1,%2,%3};"
        : "+f"(d[0]), "+f"(d[1]), "+f"(d[2]), "+f"(d[3])
        : "r"(a[0]), "r"(a[1]), "r"(a[2]), "r"(a[3]), "r"(b[0]), "r"(b[1]));
}
#endif

// ---------------- phase kernels ----------------
__global__ void absmax_both_kernel(const float* __restrict__ x, const float* __restrict__ w) {
    size_t tid0 = (size_t)blockIdx.x * blockDim.x + threadIdx.x;
    size_t stride = (size_t)gridDim.x * blockDim.x;
    const float4* p4 = (const float4*)x;
    unsigned m0 = 0;
    for (size_t i = tid0; i < (size_t)MM * KK / 4; i += stride) {
        float4 v = p4[i];
        unsigned a;
        a = __float_as_uint(v.x) & 0x7fffffffu; m0 = max(m0, a);
        a = __float_as_uint(v.y) & 0x7fffffffu; m0 = max(m0, a);
        a = __float_as_uint(v.z) & 0x7fffffffu; m0 = max(m0, a);
        a = __float_as_uint(v.w) & 0x7fffffffu; m0 = max(m0, a);
    }
    m0 = __reduce_max_sync(0xffffffffu, m0);
    if ((threadIdx.x & 31) == 0) atomicMax(&g_absmax[0], m0);

    const float4* q4 = (const float4*)w;
    unsigned m1 = 0;
    for (size_t i = tid0; i < (size_t)KK * NN / 4; i += stride) {
        float4 v = q4[i];
        unsigned a;
        a = __float_as_uint(v.x) & 0x7fffffffu; m1 = max(m1, a);
        a = __float_as_uint(v.y) & 0x7fffffffu; m1 = max(m1, a);
        a = __float_as_uint(v.z) & 0x7fffffffu; m1 = max(m1, a);
        a = __float_as_uint(v.w) & 0x7fffffffu; m1 = max(m1, a);
    }
    m1 = __reduce_max_sync(0xffffffffu, m1);
    if ((threadIdx.x & 31) == 0) atomicMax(&g_absmax[1], m1);
}

__global__ void scale_kernel() {
    float ax = __uint_as_float(g_absmax[0]);
    float aw = __uint_as_float(g_absmax[1]);
    float sx = 448.0f / ax, sw = 448.0f / aw;
    g_scales[0] = sx; g_scales[1] = sw; g_scales[2] = 1.0f / (sx * sw);
}

// Fused quantize: blocks [0, 16384) handle x (1 thread / 16B output chunk),
// blocks [16384, 17408) handle w (transpose via smem, one 128x128 tile each).
#define QX_BLOCKS ((MM / 16) * KK / 256)   // 16384
__global__ void quantize_fused_kernel(const float* __restrict__ x, const float* __restrict__ w) {
    __shared__ unsigned char sm[128 * 132];
    unsigned bid = blockIdx.x, t = threadIdx.x;
    if (bid < QX_BLOCKS) {
        // ---- x path: [M,K] fp32 -> g_xq tiled (mtile,ktile) 128x128B SW128 ----
        float sx = g_scales[0];
        unsigned idx = bid * 256 + t;     // [0, M*K/16)
        unsigned row = idx >> 8;          // K/16 = 256 chunks per row
        unsigned kc  = idx & 255;
        unsigned ktile = kc >> 3, c16 = kc & 7;
        const float4* src = (const float4*)(x + (size_t)row * KK + ktile * 128 + c16 * 16);
        unsigned out[4];
#pragma unroll
        for (int i = 0; i < 4; i++) {
            float4 v = src[i];
            unsigned b0 = q_e4m3(v.x * sx), b1 = q_e4m3(v.y * sx);
            unsigned b2 = q_e4m3(v.z * sx), b3 = q_e4m3(v.w * sx);
            out[i] = b0 | (b1 << 8) | (b2 << 16) | (b3 << 24);
        }
        unsigned tile = (row >> 7) * KTILES + ktile;
        unsigned r = row & 127;
        *(uint4*)(g_xq + (size_t)tile * TILE_BYTES + swz128(r * 128 + c16 * 16)) =
            make_uint4(out[0], out[1], out[2], out[3]);
    } else {
        // ---- w path: [K,N] fp32 -> transpose+quantize -> g_wq tiled SW128 ----
        unsigned bid2 = bid - QX_BLOCKS;            // [0, 1024)
        float swc = g_scales[1];
        unsigned ntile = bid2 >> 5, ktile = bid2 & 31;
#pragma unroll 4
        for (int i = 0; i < 16; i++) {
            unsigned f = t + i * 256;        // [0, 4096) float4 slots
            unsigned kk = f >> 5, n4 = f & 31;
            float4 v = *(const float4*)(w + (size_t)(ktile * 128 + kk) * NN + ntile * 128 + n4 * 4);
            unsigned nn = n4 * 4;
            sm[(nn + 0) * 132 + kk] = q_e4m3(v.x * swc);
            sm[(nn + 1) * 132 + kk] = q_e4m3(v.y * swc);
            sm[(nn + 2) * 132 + kk] = q_e4m3(v.z * swc);
            sm[(nn + 3) * 132 + kk] = q_e4m3(v.w * swc);
        }
        __syncthreads();
        size_t tbase = (size_t)(ntile * KTILES + ktile) * TILE_BYTES;
#pragma unroll
        for (int i = 0; i < 4; i++) {
            unsigned c = t + i * 256;        // [0, 1024) 16B chunks
            unsigned r = c >> 3, c16 = c & 7;
            unsigned base = r * 132 + c16 * 16;
            unsigned o0 = *(const unsigned*)(sm + base + 0);
            unsigned o1 = *(const unsigned*)(sm + base + 4);
            unsigned o2 = *(const unsigned*)(sm + base + 8);
            unsigned o3 = *(const unsigned*)(sm + base + 12);
            *(uint4*)(g_wq + tbase + swz128(r * 128 + c16 * 16)) = make_uint4(o0, o1, o2, o3);
        }
    }
}

// ---------------- GEMM (R6-exact dual path) ----------------
// 4096 CTAs, 288 threads. tcgen05 path (sm_103a cubin — the one that runs):
// producer warp (wid 1) feeds 3-stage cp.async.bulk pipeline; wid 0 issues
// 4x mxf8f6f4 MMA per stage with unit ue8m0 scales; LDTM epilogue by 8 warps.
__global__ void __launch_bounds__(NT) gemm_kernel(float* __restrict__ out) {
    extern __shared__ char dsm[];
    __shared__ __align__(8) unsigned long long bars[2 * STAGES + 1];
    __shared__ unsigned tmem_ptr_s;

    unsigned tid = threadIdx.x, wid = tid >> 5, lane = tid & 31;
    unsigned tile_base = (smem_u32(dsm) + 1023u) & ~1023u;
    unsigned bars_a = smem_u32(bars);
    unsigned mtile = blockIdx.x >> 5, ntile = blockIdx.x & 31;

    const unsigned char* Ag = g_xq + (size_t)mtile * KTILES * TILE_BYTES;
    const unsigned char* Bg = g_wq + (size_t)ntile * KTILES * TILE_BYTES;

#if USE_TCGEN05
    // =========================== tcgen05 path ===========================
    if (wid == 0) { TCGEN05_ALLOC(smem_u32(&tmem_ptr_s), 256); TCGEN05_RELINQUISH(); }
    if (tid == 0) {
#pragma unroll
        for (int s = 0; s < STAGES; s++) {
            MBARRIER_INIT(bars_a + 8 * s, 1);              // full[s]
            MBARRIER_INIT(bars_a + 8 * (STAGES + s), 1);   // mma_done[s]
        }
        MBARRIER_INIT(bars_a + 8 * (2 * STAGES), 1);       // all done
    }
    __syncthreads();
    unsigned tmem = tmem_ptr_s;

    // scales = 1.0 (ue8m0 = 127), replicated across all 4 subpartitions
    if (wid < 4) {
        unsigned warp_off = wid << 21;
        unsigned val = 0x7f7f7f7fu;
#pragma unroll
        for (int c = 0; c < 4; c++) TCGEN05_ST_32X32B_X1(tmem + 128 + c + warp_off, val); // SFA
#pragma unroll
        for (int c = 0; c < 4; c++) TCGEN05_ST_32X32B_X1(tmem + 132 + c + warp_off, val); // SFB
        TCGEN05_WAIT_ST();
        TCGEN05_FENCE_BEFORE();
    }
    __syncthreads();

    const uint32_t MMA_IDESC = (1u << 27) | (1u << 23) | (16u << 17); // M=128, UE8M0, N=128

    if (wid == 1) {
        if (elect_one_pred()) {
            for (int kt = 0; kt < KTILES; kt++) {
                int s = kt % STAGES, u = kt / STAGES;
                if (u > 0) MBARRIER_WAIT_PARITY_RELAXED(bars_a + 8 * (STAGES + s), (u - 1) & 1);
                uint32_t full = bars_a + 8 * s;
                MBARRIER_EXPECT_TX(full, (uint32_t)STAGE_BYTES);
                uint32_t dst = tile_base + s * STAGE_BYTES;
                bulk_g2s(dst, Ag + (size_t)kt * TILE_BYTES, TILE_BYTES, full);
                bulk_g2s(dst + TILE_BYTES, Bg + (size_t)kt * TILE_BYTES, TILE_BYTES, full);
            }
        }
    } else if (wid == 0) {
        if (elect_one_pred()) {
            TCGEN05_FENCE_AFTER();
            for (int kt = 0; kt < KTILES; kt++) {
                int s = kt % STAGES, u = kt / STAGES;
                MBARRIER_WAIT_PARITY(bars_a + 8 * s, u & 1);
                uint64_t ad = MAKE_SMEM_DESC(tile_base + s * STAGE_BYTES);
                uint64_t bd = MAKE_SMEM_DESC(tile_base + s * STAGE_BYTES + TILE_BYTES);
#pragma unroll
                for (int k = 0; k < 4; k++) {
                    mma_mxf8_ss(tmem, ad + k * 2, bd + k * 2, MMA_IDESC,
                                tmem + 128, tmem + 132, (kt > 0 || k > 0) ? 1u : 0u);
                }
                TCGEN05_COMMIT(bars_a + 8 * (STAGES + s));
            }
            TCGEN05_COMMIT(bars_a + 8 * (2 * STAGES)); // tracks ALL prior MMAs
        }
    }

    MBARRIER_WAIT_PARITY(bars_a + 8 * (2 * STAGES), 0);
    TCGEN05_FENCE_AFTER();

    // epilogue: warps 0-7; subpartition = wid&3 (rows), col half = wid>>2
    if (wid < 8) {
        float inv = g_scales[2];
        unsigned row = mtile * 128 + (wid & 3) * 32 + lane;
        unsigned chalf = (wid >> 2) * 64;
        float* op = out + (size_t)row * NN + ntile * 128 + chalf;
#pragma unroll 1
        for (int cb = 0; cb < 64; cb += 32) {
            unsigned r[32];
            TCGEN05_LD_32X32B_X32(r, tmem + chalf + cb);
            TCGEN05_WAIT_LD();
#pragma unroll
            for (int j = 0; j < 32; j += 4) {
                float4 v = make_float4(__uint_as_float(r[j]) * inv,
                                       __uint_as_float(r[j + 1]) * inv,
                                       __uint_as_float(r[j + 2]) * inv,
                                       __uint_as_float(r[j + 3]) * inv);
                *(float4*)(op + cb + j) = v;
            }
        }
    }
    __syncthreads();
    if (wid == 0) TCGEN05_DEALLOC(tmem, 256);

#else
    // =========================== mma.sync fallback ===========================
    (void)tmem_ptr_s;
    if (tid == 0) {
#pragma unroll
        for (int s = 0; s < STAGES; s++) {
            MBARRIER_INIT(bars_a + 8 * s, 1);              // full[s] (tx-based)
            MBARRIER_INIT(bars_a + 8 * (STAGES + s), 8);   // consumed[s] (8 warps)
        }
    }
    __syncthreads();

    if (wid == 8) {
        if (elect_one_pred()) {
            for (int kt = 0; kt < KTILES; kt++) {
                int s = kt % STAGES, u = kt / STAGES;
                if (u > 0) MBARRIER_WAIT_PARITY_RELAXED(bars_a + 8 * (STAGES + s), (u - 1) & 1);
                uint32_t full = bars_a + 8 * s;
                MBARRIER_EXPECT_TX(full, (uint32_t)STAGE_BYTES);
                uint32_t dst = tile_base + s * STAGE_BYTES;
                bulk_g2s(dst, Ag + (size_t)kt * TILE_BYTES, TILE_BYTES, full);
                bulk_g2s(dst + TILE_BYTES, Bg + (size_t)kt * TILE_BYTES, TILE_BYTES, full);
            }
        }
    } else {
        // 8 compute warps: 2(M) x 4(N); each computes 64x32 of the 128x128 tile
        unsigned wm = wid >> 2, wn = wid & 3;
        float d[4][4][4];
#pragma unroll
        for (int i = 0; i < 4; i++)
#pragma unroll
            for (int j = 0; j < 4; j++)
#pragma unroll
                for (int k = 0; k < 4; k++) d[i][j][k] = 0.0f;

        unsigned xorm = (lane & 7) << 4;
        unsigned aRow[4], bRow[2];
#pragma unroll
        for (int am = 0; am < 4; am++)
            aRow[am] = (wm * 64 + am * 16 + ((lane >> 3) & 1) * 8 + (lane & 7)) * 128;
#pragma unroll
        for (int p = 0; p < 2; p++)
            bRow[p] = (wn * 32 + p * 16 + (lane >> 4) * 8 + (lane & 7)) * 128;
        unsigned aColBase = (lane >> 4) << 4;         // 0 or 16
        unsigned bColBase = ((lane >> 3) & 1) << 4;   // 0 or 16

        for (int kt = 0; kt < KTILES; kt++) {
            int s = kt % STAGES, u = kt / STAGES;
            MBARRIER_WAIT_PARITY(bars_a + 8 * s, u & 1);
            uint32_t sA = tile_base + s * STAGE_BYTES;
            uint32_t sB = sA + TILE_BYTES;
#pragma unroll
            for (int kk = 0; kk < 4; kk++) {
                unsigned acol = ((unsigned)(kk * 32) + aColBase) ^ xorm;
                unsigned bcol = ((unsigned)(kk * 32) + bColBase) ^ xorm;
                unsigned a[4][4];
#pragma unroll
                for (int am = 0; am < 4; am++)
                    ldsm4(a[am][0], a[am][1], a[am][2], a[am][3], sA + aRow[am] + acol);
                unsigned b[4][2];
#pragma unroll
                for (int p = 0; p < 2; p++)
                    ldsm4(b[2 * p][0], b[2 * p][1], b[2 * p + 1][0], b[2 * p + 1][1],
                          sB + bRow[p] + bcol);
#pragma unroll
                for (int am = 0; am < 4; am++)
#pragma unroll
                    for (int bn = 0; bn < 4; bn++)
                        mma_e4m3(d[am][bn], a[am], b[bn]);
            }
            __syncwarp();
            if (lane == 0) MBARRIER_ARRIVE(bars_a + 8 * (STAGES + s));
        }

        float inv = g_scales[2];
        unsigned gID = lane >> 2, tID = lane & 3;
#pragma unroll
        for (int am = 0; am < 4; am++) {
            unsigned row0 = mtile * 128 + wm * 64 + am * 16 + gID;
#pragma unroll
            for (int bn = 0; bn < 4; bn++) {
                unsigned col = ntile * 128 + wn * 32 + bn * 8 + tID * 2;
                float2 v0 = make_float2(d[am][bn][0] * inv, d[am][bn][1] * inv);
                float2 v1 = make_float2(d[am][bn][2] * inv, d[am][bn][3] * inv);
                *(float2*)(out + (size_t)row0 * NN + col) = v0;
                *(float2*)(out + (size_t)(row0 + 8) * NN + col) = v1;
            }
        }
    }
#endif
}

// ---------------- launch ----------------
extern "C" void kernel_launch(void* const* d_in, const int* in_sizes, int n_in,
                              void* d_out, int out_size) {
    (void)in_sizes; (void)n_in; (void)out_size;
    const float* x = (const float*)d_in[0];
    const float* w = (const float*)d_in[1];
    float* out = (float*)d_out;

    cudaFuncSetAttribute(gemm_kernel, cudaFuncAttributeMaxDynamicSharedMemorySize, SMEM_DYN);

    absmax_both_kernel<<<2048, 256>>>(x, w);
    scale_kernel<<<1, 1>>>();
    quantize_fused_kernel<<<QX_BLOCKS + NTILES * KTILES, 256>>>(x, w);
    gemm_kernel<<<MTILES * NTILES, NT, SMEM_DYN>>>(out);
}